// round 7
// baseline (speedup 1.0000x reference)
#include <cuda_runtime.h>
#include <cuda_bf16.h>
#include <math.h>
#include <stdint.h>

// ---------------------------------------------------------------------------
// Swin block: B=16, C=384, H=W=56, NH=12, WS=7, SS=3, MLP=1536
// GEMMs via mma.sync tf32, CTA 256x128, warp tile 64x64 (smem-traffic-optimal)
// ---------------------------------------------------------------------------
#define TOK   50176
#define CCH   384
#define HH    56
#define WW2   56
#define NWIN  1024
#define NTOK  49
#define NHEAD 12
#define HDIM  32
#define MLPD  1536

// Scratch
__device__ float g_xbhwc[TOK * CCH];
__device__ float g_xw   [TOK * CCH];
__device__ float g_q    [TOK * CCH];
__device__ float g_k    [TOK * CCH];
__device__ float g_v    [TOK * CCH];
__device__ float g_ao   [TOK * CCH];
__device__ float g_x2   [TOK * CCH];
__device__ float g_xn2  [TOK * CCH];
__device__ float g_h1   [TOK * MLPD];
__device__ float g_y    [TOK * CCH];

__device__ __forceinline__ float tf32r(float f) {
    uint32_t u;
    asm("cvt.rna.tf32.f32 %0, %1;" : "=r"(u) : "f"(f));
    return __uint_as_float(u);
}

// ---------------------------------------------------------------------------
// tf32 mma.sync GEMM: C[M,N] = A[M,K] * B[K,N].
// CTA tile 256x128, 8 warps (4M x 2N), warp tile 64x64, k-chunk 16.
// Crosswise smem: element (k, x) at [k>>2][x][k&3] -> every fragment LDS.32
// is one contiguous 128B wavefront, conflict-free.
// MODE 0: QKV split  1: proj+winrev+residual  2: fc1+GELU  3: fc2+residual
// ---------------------------------------------------------------------------
template <int MODE>
__global__ void __launch_bounds__(256) k_gemm_mma(
    const float* __restrict__ A, const float* __restrict__ Bw,
    const float* __restrict__ bias, int K, int N, int NC)
{
    // [stage][kgroup][x][4]   A: 32KB, B: 16KB  (48KB total)
    __shared__ float As[2][4][256][4];
    __shared__ float Bs[2][4][128][4];

    const int tid = threadIdx.x;
    const int wid = tid >> 5, lane = tid & 31;
    const int gid = lane >> 2, tig = lane & 3;
    const int wm = wid >> 1, wn = wid & 1;       // 4 x 2 warp grid
    const int m0 = blockIdx.y * 256, n0 = blockIdx.x * 128;

    float acc[4][8][4];
#pragma unroll
    for (int a = 0; a < 4; a++)
#pragma unroll
        for (int b = 0; b < 8; b++)
#pragma unroll
            for (int c = 0; c < 4; c++) acc[a][b][c] = 0.f;

    // ---- global load staging ----
    // A: 256 rows x 16 k = 1024 float4; thread does 4 (row = t*64 + tid>>2)
    const int a_row = tid >> 2, a_kq = (tid & 3) * 4;
    // B: 16 k x 128 n = 2048 floats; thread does 8 scalar (coalesced in n)
    const int b_n0i = tid & 127, b_kq0 = (tid >> 7) * 4;

    float4 la[4];
    float  lb[2][4];

    auto ldg_chunk = [&](int c) {
#pragma unroll
        for (int t = 0; t < 4; t++) {
            int row = t * 64 + a_row;
            la[t] = *reinterpret_cast<const float4*>(
                A + (size_t)(m0 + row) * K + c * 16 + a_kq);
        }
#pragma unroll
        for (int t = 0; t < 2; t++) {
            int kq = t * 8 + b_kq0;
#pragma unroll
            for (int j = 0; j < 4; j++)
                lb[t][j] = __ldg(Bw + (size_t)(c * 16 + kq + j) * N + n0 + b_n0i);
        }
    };
    auto sts_chunk = [&](int s) {
#pragma unroll
        for (int t = 0; t < 4; t++) {
            int row = t * 64 + a_row;
            float4 va;
            va.x = tf32r(la[t].x); va.y = tf32r(la[t].y);
            va.z = tf32r(la[t].z); va.w = tf32r(la[t].w);
            *reinterpret_cast<float4*>(&As[s][a_kq >> 2][row][0]) = va;
        }
#pragma unroll
        for (int t = 0; t < 2; t++) {
            int kq = t * 8 + b_kq0;
            float4 vb;
            vb.x = tf32r(lb[t][0]); vb.y = tf32r(lb[t][1]);
            vb.z = tf32r(lb[t][2]); vb.w = tf32r(lb[t][3]);
            *reinterpret_cast<float4*>(&Bs[s][kq >> 2][b_n0i][0]) = vb;
        }
    };

    const int ma = wm * 64 + gid;       // base m within tile (frag row)
    const int na = wn * 64 + gid;       // base n within tile

    auto compute = [&](int s) {
#pragma unroll
        for (int ks = 0; ks < 2; ks++) {
            const int kg = ks * 2;
            uint32_t af[4][4], bf[8][2];
#pragma unroll
            for (int mi = 0; mi < 4; mi++) {
                int m = ma + mi * 16;
                af[mi][0] = __float_as_uint(As[s][kg][m][tig]);
                af[mi][1] = __float_as_uint(As[s][kg][m + 8][tig]);
                af[mi][2] = __float_as_uint(As[s][kg + 1][m][tig]);
                af[mi][3] = __float_as_uint(As[s][kg + 1][m + 8][tig]);
            }
#pragma unroll
            for (int ni = 0; ni < 8; ni++) {
                int n = na + ni * 8;
                bf[ni][0] = __float_as_uint(Bs[s][kg][n][tig]);
                bf[ni][1] = __float_as_uint(Bs[s][kg + 1][n][tig]);
            }
#pragma unroll
            for (int mi = 0; mi < 4; mi++)
#pragma unroll
                for (int ni = 0; ni < 8; ni++)
                    asm volatile(
                        "mma.sync.aligned.m16n8k8.row.col.f32.tf32.tf32.f32 "
                        "{%0,%1,%2,%3},{%4,%5,%6,%7},{%8,%9},{%0,%1,%2,%3};"
                        : "+f"(acc[mi][ni][0]), "+f"(acc[mi][ni][1]),
                          "+f"(acc[mi][ni][2]), "+f"(acc[mi][ni][3])
                        : "r"(af[mi][0]), "r"(af[mi][1]),
                          "r"(af[mi][2]), "r"(af[mi][3]),
                          "r"(bf[ni][0]), "r"(bf[ni][1]));
        }
    };

    int s = 0;
    ldg_chunk(0);
    sts_chunk(0);
    __syncthreads();
    for (int c = 0; c < NC; c++) {
        if (c + 1 < NC) ldg_chunk(c + 1);
        compute(s);
        if (c + 1 < NC) sts_chunk(s ^ 1);
        __syncthreads();
        s ^= 1;
    }

    // ---------------- epilogue: fused scatter from accumulators -------------
    const float qscale = 0.17677669529663687f;

    auto store_pair = [&](int m, int n, float vx, float vy) {
        vx += __ldg(&bias[n]);
        vy += __ldg(&bias[n + 1]);
        if (MODE == 0) {
            int tq = n / CCH;
            int rem = n - tq * CCH;
            int head = rem >> 5, hd = rem & 31;
            int win = m / NTOK, tokn = m - win * NTOK;
            float scl = (tq == 0) ? qscale : 1.0f;
            float* dst = (tq == 0) ? g_q : (tq == 1) ? g_k : g_v;
            size_t o = (((size_t)(win * NHEAD + head)) * NTOK + tokn) * HDIM + hd;
            *reinterpret_cast<float2*>(dst + o) = make_float2(vx * scl, vy * scl);
        } else if (MODE == 1) {
            int win = m / NTOK, tokn = m - win * NTOK;
            int b = win >> 6, widx = win & 63;
            int h = (widx >> 3) * 7 + tokn / 7 + 3; if (h >= HH)  h -= HH;
            int w = (widx & 7) * 7 + tokn % 7 + 3;  if (w >= WW2) w -= WW2;
            size_t tk = ((size_t)(b * HH + h)) * WW2 + w;
            float2 r = *reinterpret_cast<const float2*>(g_xbhwc + tk * CCH + n);
            *reinterpret_cast<float2*>(g_x2 + tk * CCH + n) =
                make_float2(vx + r.x, vy + r.y);
        } else if (MODE == 2) {
            vx = 0.5f * vx * (1.0f + erff(vx * 0.70710678118654752f));
            vy = 0.5f * vy * (1.0f + erff(vy * 0.70710678118654752f));
            *reinterpret_cast<float2*>(g_h1 + (size_t)m * MLPD + n) =
                make_float2(vx, vy);
        } else {
            float2 r = *reinterpret_cast<const float2*>(g_x2 + (size_t)m * CCH + n);
            *reinterpret_cast<float2*>(g_y + (size_t)m * CCH + n) =
                make_float2(vx + r.x, vy + r.y);
        }
    };

#pragma unroll
    for (int mi = 0; mi < 4; mi++) {
#pragma unroll
        for (int ni = 0; ni < 8; ni++) {
            int m = m0 + wm * 64 + mi * 16 + gid;
            int n = n0 + wn * 64 + ni * 8 + tig * 2;
            store_pair(m,     n, acc[mi][ni][0], acc[mi][ni][1]);
            store_pair(m + 8, n, acc[mi][ni][2], acc[mi][ni][3]);
        }
    }
}

// ---------------------------------------------------------------------------
// K1: LN1 + NCHW->NHWC + shifted-window partition
// ---------------------------------------------------------------------------
__global__ void __launch_bounds__(256) k_ln1_window(
    const float* __restrict__ x, const float* __restrict__ g1,
    const float* __restrict__ b1)
{
    extern __shared__ float sm[];
    __shared__ float smu[56], srs[56];
    const int bh = blockIdx.x;
    const int b = bh / HH, h = bh % HH;
    const int tid = threadIdx.x;
    const float* xp = x + (size_t)b * CCH * (HH * WW2) + (size_t)h * WW2;

    for (int idx = tid; idx < CCH * WW2; idx += 256) {
        int c = idx / WW2, w = idx % WW2;
        sm[c * 57 + w] = xp[(size_t)c * (HH * WW2) + w];
    }
    __syncthreads();
    if (tid < WW2) {
        float s = 0.f, s2 = 0.f;
        for (int c = 0; c < CCH; c++) {
            float t = sm[c * 57 + tid];
            s += t; s2 += t * t;
        }
        float mu = s * (1.0f / CCH);
        smu[tid] = mu;
        srs[tid] = rsqrtf(s2 * (1.0f / CCH) - mu * mu + 1e-5f);
    }
    __syncthreads();

    int hp = h - 3; if (hp < 0) hp += HH;
    const int wh = hp / 7, rr = hp % 7;
    for (int idx = tid; idx < WW2 * CCH; idx += 256) {
        int w = idx / CCH, c = idx % CCH;
        float val = sm[c * 57 + w];
        size_t tok = (size_t)(b * HH + h) * WW2 + w;
        g_xbhwc[tok * CCH + c] = val;
        float nv = (val - smu[w]) * srs[w] * __ldg(&g1[c]) + __ldg(&b1[c]);
        int wp = w - 3; if (wp < 0) wp += WW2;
        int win = (b * 8 + wh) * 8 + wp / 7;
        g_xw[((size_t)win * NTOK + rr * 7 + wp % 7) * CCH + c] = nv;
    }
}

// ---------------------------------------------------------------------------
// K3: windowed attention
// ---------------------------------------------------------------------------
__global__ void __launch_bounds__(256) k_attn()
{
    __shared__ float sq[NTOK * 33], sk[NTOK * 33], sv[NTOK * 33];
    __shared__ float sS[NTOK * 52];
    __shared__ int   sid[NTOK];

    const int win = blockIdx.x / NHEAD;
    const int nh  = blockIdx.x % NHEAD;
    const int tid = threadIdx.x;
    const size_t base = ((size_t)(win * NHEAD + nh)) * NTOK * HDIM;

    for (int idx = tid; idx < NTOK * HDIM; idx += 256) {
        int r = idx >> 5, c = idx & 31;
        sq[r * 33 + c] = g_q[base + idx];
        sk[r * 33 + c] = g_k[base + idx];
        sv[r * 33 + c] = g_v[base + idx];
    }
    if (tid < NTOK) {
        int widx = win & 63;
        int hp = (widx >> 3) * 7 + tid / 7;
        int wp = (widx & 7) * 7 + tid % 7;
        int hr = (hp < 49) ? 0 : (hp < 53 ? 1 : 2);
        int wr = (wp < 49) ? 0 : (wp < 53 ? 1 : 2);
        sid[tid] = hr * 3 + wr;
    }
    __syncthreads();

    for (int idx = tid; idx < NTOK * NTOK; idx += 256) {
        int i = idx / NTOK, j = idx % NTOK;
        float s = 0.f;
#pragma unroll
        for (int l = 0; l < HDIM; l++) s += sq[i * 33 + l] * sk[j * 33 + l];
        if (sid[i] != sid[j]) s -= 100.0f;
        sS[i * 52 + j] = s;
    }
    __syncthreads();

    const int warp = tid >> 5, lane = tid & 31;
    for (int i = warp; i < NTOK; i += 8) {
        float mx = -1e30f;
        for (int j = lane; j < NTOK; j += 32) mx = fmaxf(mx, sS[i * 52 + j]);
#pragma unroll
        for (int o = 16; o; o >>= 1) mx = fmaxf(mx, __shfl_xor_sync(0xffffffffu, mx, o));
        float sum = 0.f;
        for (int j = lane; j < NTOK; j += 32) {
            float e = __expf(sS[i * 52 + j] - mx);
            sS[i * 52 + j] = e;
            sum += e;
        }
#pragma unroll
        for (int o = 16; o; o >>= 1) sum += __shfl_xor_sync(0xffffffffu, sum, o);
        float inv = 1.0f / sum;
        for (int j = lane; j < NTOK; j += 32) sS[i * 52 + j] *= inv;
    }
    __syncthreads();

    for (int idx = tid; idx < NTOK * HDIM; idx += 256) {
        int i = idx >> 5, d = idx & 31;
        float o = 0.f;
#pragma unroll 7
        for (int j = 0; j < NTOK; j++) o += sS[i * 52 + j] * sv[j * 33 + d];
        g_ao[((size_t)(win * NTOK + i)) * CCH + nh * HDIM + d] = o;
    }
}

// ---------------------------------------------------------------------------
// K4: LN2
// ---------------------------------------------------------------------------
__global__ void __launch_bounds__(256) k_ln2(
    const float* __restrict__ g2, const float* __restrict__ b2)
{
    const int warp = threadIdx.x >> 5, lane = threadIdx.x & 31;
    const size_t tok = (size_t)blockIdx.x * 8 + warp;
    const float* p = g_x2 + tok * CCH;
    float v[12];
    float s = 0.f, s2 = 0.f;
#pragma unroll
    for (int i = 0; i < 12; i++) {
        v[i] = p[lane + i * 32];
        s += v[i]; s2 += v[i] * v[i];
    }
#pragma unroll
    for (int o = 16; o; o >>= 1) {
        s  += __shfl_xor_sync(0xffffffffu, s,  o);
        s2 += __shfl_xor_sync(0xffffffffu, s2, o);
    }
    float mu = s * (1.0f / CCH);
    float rs = rsqrtf(s2 * (1.0f / CCH) - mu * mu + 1e-5f);
    float* q = g_xn2 + tok * CCH;
#pragma unroll
    for (int i = 0; i < 12; i++) {
        int c = lane + i * 32;
        q[c] = (v[i] - mu) * rs * __ldg(&g2[c]) + __ldg(&b2[c]);
    }
}

// ---------------------------------------------------------------------------
// K5: NHWC -> NCHW
// ---------------------------------------------------------------------------
__global__ void __launch_bounds__(256) k_tr(float* __restrict__ out)
{
    __shared__ float t[32 * 57];
    const int bh = blockIdx.x;
    const int c0 = blockIdx.y * 32;
    const int b = bh / HH, h = bh % HH;
    const float* yp = g_y + (size_t)bh * WW2 * CCH + c0;

    for (int idx = threadIdx.x; idx < WW2 * 32; idx += 256) {
        int w = idx >> 5, cc = idx & 31;
        t[cc * 57 + w] = yp[(size_t)w * CCH + cc];
    }
    __syncthreads();
    float* op = out + (size_t)b * CCH * (HH * WW2) + (size_t)c0 * (HH * WW2) + h * WW2;
    for (int idx = threadIdx.x; idx < WW2 * 32; idx += 256) {
        int cc = idx / WW2, w = idx % WW2;
        op[(size_t)cc * (HH * WW2) + w] = t[cc * 57 + w];
    }
}

// ---------------------------------------------------------------------------
extern "C" void kernel_launch(void* const* d_in, const int* in_sizes, int n_in,
                              void* d_out, int out_size)
{
    const float* x       = (const float*)d_in[0];
    const float* norm1_g = (const float*)d_in[1];
    const float* norm1_b = (const float*)d_in[2];
    const float* qkv_w   = (const float*)d_in[3];
    const float* qkv_b   = (const float*)d_in[4];
    const float* proj_w  = (const float*)d_in[5];
    const float* proj_b  = (const float*)d_in[6];
    const float* norm2_g = (const float*)d_in[7];
    const float* norm2_b = (const float*)d_in[8];
    const float* fc1_w   = (const float*)d_in[9];
    const float* fc1_b   = (const float*)d_in[10];
    const float* fc2_w   = (const float*)d_in[11];
    const float* fc2_b   = (const float*)d_in[12];

    float *p_xw, *p_ao, *p_xn2, *p_h1;
    cudaGetSymbolAddress((void**)&p_xw,  g_xw);
    cudaGetSymbolAddress((void**)&p_ao,  g_ao);
    cudaGetSymbolAddress((void**)&p_xn2, g_xn2);
    cudaGetSymbolAddress((void**)&p_h1,  g_h1);

    const int ln1_smem = 384 * 57 * sizeof(float);
    cudaFuncSetAttribute(k_ln1_window,
                         cudaFuncAttributeMaxDynamicSharedMemorySize, ln1_smem);

    // 1) LN1 + transpose + shifted window partition
    k_ln1_window<<<16 * HH, 256, ln1_smem>>>(x, norm1_g, norm1_b);

    // 2) QKV GEMM: [50176,384] x [384,1152]
    k_gemm_mma<0><<<dim3(1152 / 128, TOK / 256), 256>>>(
        p_xw, qkv_w, qkv_b, 384, 1152, 24);

    // 3) windowed attention
    k_attn<<<NWIN * NHEAD, 256>>>();

    // 4) proj GEMM + window reverse + residual
    k_gemm_mma<1><<<dim3(CCH / 128, TOK / 256), 256>>>(
        p_ao, proj_w, proj_b, 384, CCH, 24);

    // 5) LN2
    k_ln2<<<TOK / 8, 256>>>(norm2_g, norm2_b);

    // 6) fc1 + GELU
    k_gemm_mma<2><<<dim3(MLPD / 128, TOK / 256), 256>>>(
        p_xn2, fc1_w, fc1_b, 384, MLPD, 24);

    // 7) fc2 + residual
    k_gemm_mma<3><<<dim3(CCH / 128, TOK / 256), 256>>>(
        p_h1, fc2_w, fc2_b, 1536, CCH, 96);

    // 8) NHWC -> NCHW
    k_tr<<<dim3(16 * HH, CCH / 32), 256>>>((float*)d_out);
}